// round 2
// baseline (speedup 1.0000x reference)
#include <cuda_runtime.h>

// SmoothAPLoss: loss = sum_{i in pos, j in neg} relu(p_j - p_i + DELTA) / max(num_pos, 1)
// p_i = softmax(pred_i)[1] = sigmoid(x1 - x0)
// NOTE: labels are int32 on device (JAX default x64-disabled downcasts int64).

#define DELTA 0.01f
#define MAXN 16384
#define TPB 256
#define KPOS 4
#define TILE 2048

__device__ float  g_neg[MAXN];    // probabilities of negatives (compacted)
__device__ float  g_posc[MAXN];   // (p - DELTA) of positives (compacted)
__device__ int    g_nneg;
__device__ int    g_npos;
__device__ double g_total;

__global__ void init_kernel() {
    g_nneg = 0;
    g_npos = 0;
    g_total = 0.0;
}

__global__ void prob_kernel(const float* __restrict__ pred,
                            const int* __restrict__ lab, int n) {
    int i = blockIdx.x * blockDim.x + threadIdx.x;
    if (i >= n) return;
    float x0 = pred[2 * i];
    float x1 = pred[2 * i + 1];
    // softmax over 2 classes, prob of class 1 == sigmoid(x1 - x0)
    float p = 1.0f / (1.0f + __expf(x0 - x1));
    int l = lab[i];
    if (l == 1) {
        int k = atomicAdd(&g_npos, 1);
        g_posc[k] = p - DELTA;
    } else {
        int k = atomicAdd(&g_nneg, 1);
        g_neg[k] = p;
    }
}

// grid.x covers positive slots (gx * TPB * KPOS >= n >= npos), grid.y splits negatives.
__global__ void pair_kernel() {
    __shared__ float s[TILE];

    const int npos = g_npos;
    const int nneg = g_nneg;

    // Register-block KPOS positives per thread. Padded slots get c = 1e30
    // so fmaxf(v - c, 0) == 0 exactly (v - 1e30 is a large negative, never NaN).
    float c[KPOS];
    int base = blockIdx.x * (TPB * KPOS) + threadIdx.x;
#pragma unroll
    for (int k = 0; k < KPOS; k++) {
        int ip = base + k * TPB;
        c[k] = (ip < npos) ? g_posc[ip] : 1e30f;
    }

    float acc[KPOS];
#pragma unroll
    for (int k = 0; k < KPOS; k++) acc[k] = 0.0f;

    for (int t0 = blockIdx.y * TILE; t0 < nneg; t0 += gridDim.y * TILE) {
        int cnt = min(TILE, nneg - t0);
        __syncthreads();
        for (int j = threadIdx.x; j < cnt; j += TPB) s[j] = g_neg[t0 + j];
        __syncthreads();

        int j = 0;
        // unrolled-by-4 inner loop over negatives in smem (broadcast reads)
        for (; j + 4 <= cnt; j += 4) {
            float v0 = s[j + 0], v1 = s[j + 1], v2 = s[j + 2], v3 = s[j + 3];
#pragma unroll
            for (int k = 0; k < KPOS; k++) {
                acc[k] += fmaxf(v0 - c[k], 0.0f);
                acc[k] += fmaxf(v1 - c[k], 0.0f);
                acc[k] += fmaxf(v2 - c[k], 0.0f);
                acc[k] += fmaxf(v3 - c[k], 0.0f);
            }
        }
        for (; j < cnt; j++) {
            float v = s[j];
#pragma unroll
            for (int k = 0; k < KPOS; k++) acc[k] += fmaxf(v - c[k], 0.0f);
        }
    }

    float a = acc[0] + acc[1] + acc[2] + acc[3];

    // block reduction
    for (int off = 16; off > 0; off >>= 1)
        a += __shfl_down_sync(0xFFFFFFFFu, a, off);

    __shared__ float wsum[TPB / 32];
    if ((threadIdx.x & 31) == 0) wsum[threadIdx.x >> 5] = a;
    __syncthreads();
    if (threadIdx.x < TPB / 32) {
        float b = wsum[threadIdx.x];
#pragma unroll
        for (int off = (TPB / 64); off > 0; off >>= 1)
            b += __shfl_down_sync(0xFFu, b, off);
        if (threadIdx.x == 0) atomicAdd(&g_total, (double)b);
    }
}

__global__ void final_kernel(float* __restrict__ out) {
    double denom = (double)max(g_npos, 1);
    out[0] = (float)(g_total / denom);
}

extern "C" void kernel_launch(void* const* d_in, const int* in_sizes, int n_in,
                              void* d_out, int out_size) {
    const float* pred = (const float*)d_in[0];
    const int* lab = (const int*)d_in[1];
    float* out = (float*)d_out;
    int n = in_sizes[1];  // number of labels (= N)

    init_kernel<<<1, 1>>>();
    prob_kernel<<<(n + TPB - 1) / TPB, TPB>>>(pred, lab, n);

    int gx = (n + TPB * KPOS - 1) / (TPB * KPOS);  // 16 for N=16384
    dim3 grid(gx, 32);
    pair_kernel<<<grid, TPB>>>();

    final_kernel<<<1, 1>>>(out);
}

// round 3
// speedup vs baseline: 2.3000x; 2.3000x over previous
#include <cuda_runtime.h>

// SmoothAPLoss: loss = sum_{i in pos, j in neg} relu(p_j - p_i + DELTA) / max(num_pos, 1)
// p_i = softmax(pred_i)[1] = sigmoid(x1 - x0).  Labels are int32 on device.
//
// Pair trick: sum_j relu(v_j - c) = sum_j max(v_j, c) - cnt * c
// -> inner loop is 1 FMNMX + 1 FADD per pair (fma/alu pipes balanced).

#define DELTA 0.01f
#define MAXN 16384
#define TPB 256
#define KPOS 2
#define GX 32          // GX * TPB * KPOS = 16384 pos slots
#define GY 32
#define MAXCHUNK 512   // ceil(MAXN / GY)

__device__ float g_neg[MAXN];
__device__ float g_posc[MAXN];

struct Ctrl {
    int npos;
    int nneg;
    int done;
    int pad;
    double total;
};
__device__ Ctrl g_ctrl;

__global__ void prob_kernel(const float2* __restrict__ pred,
                            const int* __restrict__ lab, int n) {
    int i = blockIdx.x * blockDim.x + threadIdx.x;
    if (i >= n) return;
    float2 x = pred[i];
    float p = 1.0f / (1.0f + __expf(x.x - x.y));   // sigmoid(x1 - x0)
    bool is_pos = (lab[i] == 1);

    unsigned full = 0xFFFFFFFFu;
    unsigned m_pos = __ballot_sync(full, is_pos);
    unsigned m_neg = ~m_pos;  // all lanes valid (n multiple of 32 here; guarded below anyway)
    int lane = threadIdx.x & 31;
    unsigned lt = (1u << lane) - 1u;

    int base_pos = 0, base_neg = 0;
    if (lane == 0) {
        base_pos = atomicAdd(&g_ctrl.npos, __popc(m_pos));
        base_neg = atomicAdd(&g_ctrl.nneg, __popc(m_neg));
    }
    base_pos = __shfl_sync(full, base_pos, 0);
    base_neg = __shfl_sync(full, base_neg, 0);

    if (is_pos) g_posc[base_pos + __popc(m_pos & lt)] = p - DELTA;
    else        g_neg[base_neg + __popc(m_neg & lt)] = p;
}

__global__ void pair_kernel(float* __restrict__ out) {
    __shared__ float s[MAXCHUNK];

    const int npos = g_ctrl.npos;
    const int nneg = g_ctrl.nneg;

    // negative chunk for this y-block
    int chunk = (nneg + (int)gridDim.y - 1) / (int)gridDim.y;
    int start = blockIdx.y * chunk;
    int end = min(start + chunk, nneg);
    int cnt = end - start;

    int slot0 = blockIdx.x * (TPB * KPOS);
    bool block_active = (slot0 < npos) && (cnt > 0);  // uniform across block

    float a = 0.0f;
    if (block_active) {
        for (int j = threadIdx.x; j < cnt; j += TPB) s[j] = g_neg[start + j];
        __syncthreads();

        float c[KPOS];
        float flag[KPOS];
        float acc[KPOS];
#pragma unroll
        for (int k = 0; k < KPOS; k++) {
            int ip = slot0 + k * TPB + threadIdx.x;
            bool v = (ip < npos);
            c[k] = v ? g_posc[ip] : 0.0f;
            flag[k] = v ? 1.0f : 0.0f;
            acc[k] = 0.0f;
        }

        int j = 0;
        for (; j + 4 <= cnt; j += 4) {
            float v0 = s[j], v1 = s[j + 1], v2 = s[j + 2], v3 = s[j + 3];
#pragma unroll
            for (int k = 0; k < KPOS; k++) {
                acc[k] += fmaxf(v0, c[k]);
                acc[k] += fmaxf(v1, c[k]);
                acc[k] += fmaxf(v2, c[k]);
                acc[k] += fmaxf(v3, c[k]);
            }
        }
        for (; j < cnt; j++) {
            float v = s[j];
#pragma unroll
            for (int k = 0; k < KPOS; k++) acc[k] += fmaxf(v, c[k]);
        }

        float fcnt = (float)cnt;
#pragma unroll
        for (int k = 0; k < KPOS; k++)
            a += flag[k] * (acc[k] - fcnt * c[k]);
    }

    // block reduction
    unsigned full = 0xFFFFFFFFu;
    for (int off = 16; off > 0; off >>= 1)
        a += __shfl_down_sync(full, a, off);

    __shared__ float wsum[TPB / 32];
    if ((threadIdx.x & 31) == 0) wsum[threadIdx.x >> 5] = a;
    __syncthreads();
    if (threadIdx.x == 0) {
        float b = 0.0f;
#pragma unroll
        for (int w = 0; w < TPB / 32; w++) b += wsum[w];
        if (b != 0.0f) atomicAdd(&g_ctrl.total, (double)b);
        __threadfence();
        int d = atomicAdd(&g_ctrl.done, 1);
        if (d == (int)(gridDim.x * gridDim.y) - 1) {
            // all other blocks' totals are visible (fence before their done-add)
            double denom = (double)max(g_ctrl.npos, 1);
            out[0] = (float)(g_ctrl.total / denom);
        }
    }
}

extern "C" void kernel_launch(void* const* d_in, const int* in_sizes, int n_in,
                              void* d_out, int out_size) {
    const float2* pred = (const float2*)d_in[0];
    const int* lab = (const int*)d_in[1];
    float* out = (float*)d_out;
    int n = in_sizes[1];  // N labels

    void* ctrl_addr = nullptr;
    cudaGetSymbolAddress(&ctrl_addr, g_ctrl);
    cudaMemsetAsync(ctrl_addr, 0, sizeof(Ctrl));

    prob_kernel<<<(n + TPB - 1) / TPB, TPB>>>(pred, lab, n);

    dim3 grid(GX, GY);
    pair_kernel<<<grid, TPB>>>(out);
}

// round 4
// speedup vs baseline: 2.3108x; 1.0047x over previous
#include <cuda_runtime.h>

// SmoothAPLoss, fully fused single kernel + one memset node.
// loss = sum_{pos i, neg j} relu(p_j - p_i + DELTA) / max(npos, 1)
// p = sigmoid(x1 - x0).  Labels int32 on device.
// Identity: sum_j relu(v_j - c) = sum_j max(v_j, c) - cnt*c  (c = p_pos - DELTA)
// Padded tile slots hold -1.0f: max(-1, c) = c (c > -DELTA), net contribution 0.

#define DELTA 0.01f
#define MAXN 16384
#define TPB 256
#define NBLK 512
#define XT 16            // positive tiles
#define YT 32            // negative tiles (XT * YT == NBLK)
#define SMAX 516         // ceil(MAXN/YT)=512 + float4 pad

__device__ float g_neg[MAXN];
__device__ float g_posc[MAXN];

struct Ctrl {
    int npos, nneg, arrive, done;
    double total;
};
__device__ Ctrl g_ctrl;

__device__ __forceinline__ void grid_sync(int phase) {
    __threadfence();
    __syncthreads();
    if (threadIdx.x == 0) {
        atomicAdd(&g_ctrl.arrive, 1);
        while (*(volatile int*)&g_ctrl.arrive < phase * NBLK) { }
    }
    __syncthreads();
}

__global__ void __launch_bounds__(TPB)
fused_kernel(const float2* __restrict__ pred, const int* __restrict__ lab,
             int n, float* __restrict__ out) {
    __shared__ float s[SMAX];
    __shared__ float wsum[TPB / 32];
    const int tid = threadIdx.x;
    const int b = blockIdx.x;
    const unsigned full = 0xFFFFFFFFu;

    // ---- phase 1: probability + warp-aggregated compaction (warp 0) ----
    const int items = (n + NBLK - 1) / NBLK;   // 32 for N=16384
    if (tid < 32) {
        int lane = tid;
        unsigned lt = (1u << lane) - 1u;
        int i0 = b * items;
        int rounds = (items + 31) / 32;
        for (int r = 0; r < rounds; r++) {
            int i = i0 + r * 32 + lane;
            bool valid = (i < n) && (i < i0 + items);
            float p = 0.0f;
            bool is_pos = false;
            if (valid) {
                float2 xv = pred[i];
                p = 1.0f / (1.0f + __expf(xv.x - xv.y));
                is_pos = (lab[i] == 1);
            }
            unsigned mp = __ballot_sync(full, valid && is_pos);
            unsigned mn = __ballot_sync(full, valid && !is_pos);
            int bp = 0, bn = 0;
            if (lane == 0) {
                bp = atomicAdd(&g_ctrl.npos, __popc(mp));
                bn = atomicAdd(&g_ctrl.nneg, __popc(mn));
            }
            bp = __shfl_sync(full, bp, 0);
            bn = __shfl_sync(full, bn, 0);
            if (valid) {
                if (is_pos) g_posc[bp + __popc(mp & lt)] = p - DELTA;
                else        g_neg[bn + __popc(mn & lt)] = p;
            }
        }
    }

    grid_sync(1);

    // ---- phase 2: pairwise sum ----
    const int npos = g_ctrl.npos;
    const int nneg = g_ctrl.nneg;

    const int x = b & (XT - 1);
    const int y = b >> 4;

    // this block's negative chunk -> smem (padded to multiple of 4)
    int chunk_n = (nneg + YT - 1) / YT;
    int ns = y * chunk_n;
    int ne = min(ns + chunk_n, nneg);
    int cnt = max(ne - ns, 0);
    int cnt4 = (cnt + 3) & ~3;
    for (int j = tid; j < cnt4; j += TPB)
        s[j] = (j < cnt) ? g_neg[ns + j] : -1.0f;
    __syncthreads();

    // this block's positive chunk
    int chunk_p = (npos + XT - 1) / XT;
    int ps = x * chunk_p;
    int pe = min(ps + chunk_p, npos);

    float a = 0.0f;
    const float fcnt = (float)cnt4;
    const float4* s4 = (const float4*)s;
    const int m = cnt4 >> 2;

    for (int ip = ps + 2 * tid; ip < pe; ip += 2 * TPB) {
        float c0 = g_posc[ip];
        bool h1 = (ip + 1 < pe);
        float c1 = h1 ? g_posc[ip + 1] : c0;
        float a0 = 0.0f, a1 = 0.0f;
        for (int q = 0; q < m; q++) {
            float4 v = s4[q];
            a0 += fmaxf(v.x, c0);
            a1 += fmaxf(v.x, c1);
            a0 += fmaxf(v.y, c0);
            a1 += fmaxf(v.y, c1);
            a0 += fmaxf(v.z, c0);
            a1 += fmaxf(v.z, c1);
            a0 += fmaxf(v.w, c0);
            a1 += fmaxf(v.w, c1);
        }
        a += (a0 - fcnt * c0);
        if (h1) a += (a1 - fcnt * c1);
    }

    // ---- block reduction + finalize ----
    for (int off = 16; off > 0; off >>= 1)
        a += __shfl_down_sync(full, a, off);
    if ((tid & 31) == 0) wsum[tid >> 5] = a;
    __syncthreads();
    if (tid == 0) {
        float t = 0.0f;
#pragma unroll
        for (int w = 0; w < TPB / 32; w++) t += wsum[w];
        if (t != 0.0f) atomicAdd(&g_ctrl.total, (double)t);
        __threadfence();
        if (atomicAdd(&g_ctrl.done, 1) == NBLK - 1) {
            double denom = (double)max(g_ctrl.npos, 1);
            out[0] = (float)(g_ctrl.total / denom);
        }
    }
}

extern "C" void kernel_launch(void* const* d_in, const int* in_sizes, int n_in,
                              void* d_out, int out_size) {
    const float2* pred = (const float2*)d_in[0];
    const int* lab = (const int*)d_in[1];
    float* out = (float*)d_out;
    int n = in_sizes[1];

    void* ctrl_addr = nullptr;
    cudaGetSymbolAddress(&ctrl_addr, g_ctrl);
    cudaMemsetAsync(ctrl_addr, 0, sizeof(Ctrl));

    fused_kernel<<<NBLK, TPB>>>(pred, lab, n, out);
}